// round 8
// baseline (speedup 1.0000x reference)
#include <cuda_runtime.h>
#include <cuda_fp16.h>
#include <cstdint>

// ============================================================================
// IterativeFixedPoint: z_{k+1} = tanh(z_k W^T + b + x), z0 = 0, 25 iterations.
// B=32768, F=256.  (sm_103 target: no tcgen05 -> legacy mma.sync HMMA)
//
// R8: THREE tiles in rotation, each with DOUBLE-BUFFERED A slots -> every
// epi-write -> mma-read dependency spans 2 windows, so a barrier is needed
// only after every SECOND window (half of R7's). Warps get a full window of
// drift slack to hide ldmatrix latency. B (W) fragments: 14/16 k-steps cached
// in registers, 2 k-steps from a compact 20.5KB SMEM W-slice (frees regs for
// the 3rd accumulator). c = x+b in SMEM fp32. tanh.approx epilogue.
// z1 = tanh(c) computed directly (z0=0) -> 24 MMA rounds.
// ============================================================================

static constexpr int F       = 256;
static constexpr int MB      = 32;
static constexpr int THREADS = 256;          // 8 warps
static constexpr int GRID    = 152;

static constexpr int ROWB    = 528;          // A/W row: 256 halves + 16B pad
static constexpr int A_BYTES = MB * ROWB;    // 16896
// SMEM map (region 0..135168 first holds W, then is reused for A slots + C):
//   A slots: (2*t+s)*A_BYTES, t=0..2, s=0..1            -> 101376
//   C buffers (fp32 SoA): SMEM_C_BASE + t*C_BYTES        -> +98304
//   W k-slice (k=224..255) for the 2 uncached k-steps    -> +20480
static constexpr int SMEM_C_BASE = 6 * A_BYTES;            // 101376
static constexpr int C_BYTES     = 32768;
static constexpr int SMEM_WK     = SMEM_C_BASE + 3 * C_BYTES;  // 199680
static constexpr int WK_ROWB     = 80;                     // 64B data + 16B pad
static constexpr int SMEM_BYTES  = SMEM_WK + 256 * WK_ROWB;    // 220160

// A slot byte offsets
static constexpr uint32_t A00 = 0 * A_BYTES, A01 = 1 * A_BYTES;
static constexpr uint32_t A10 = 2 * A_BYTES, A11 = 3 * A_BYTES;
static constexpr uint32_t A20 = 4 * A_BYTES, A21 = 5 * A_BYTES;
static constexpr uint32_t C0 = SMEM_C_BASE;
static constexpr uint32_t C1 = SMEM_C_BASE + C_BYTES;
static constexpr uint32_t C2 = SMEM_C_BASE + 2 * C_BYTES;

__device__ __forceinline__ uint32_t smem_u32(const void* p) {
    uint32_t a;
    asm("{ .reg .u64 t; cvta.to.shared.u64 t, %1; cvt.u32.u64 %0, t; }"
        : "=r"(a) : "l"(p));
    return a;
}

__device__ __forceinline__ void ldsm_x4(uint32_t r[4], uint32_t addr) {
    asm volatile("ldmatrix.sync.aligned.m8n8.x4.shared.b16 {%0,%1,%2,%3}, [%4];"
                 : "=r"(r[0]), "=r"(r[1]), "=r"(r[2]), "=r"(r[3])
                 : "r"(addr));
}

__device__ __forceinline__ void mma16816(float d[4], const uint32_t a[4],
                                         const uint32_t b0, const uint32_t b1) {
    asm volatile(
        "mma.sync.aligned.m16n8k16.row.col.f32.f16.f16.f32 "
        "{%0,%1,%2,%3}, {%4,%5,%6,%7}, {%8,%9}, {%0,%1,%2,%3};"
        : "+f"(d[0]), "+f"(d[1]), "+f"(d[2]), "+f"(d[3])
        : "r"(a[0]), "r"(a[1]), "r"(a[2]), "r"(a[3]), "r"(b0), "r"(b1));
}

__device__ __forceinline__ float tanhap(float s) {
    float r;
    asm("tanh.approx.f32 %0, %1;" : "=f"(r) : "f"(s));
    return r;
}

// one epilogue chunk: pair p (0..15) of this thread's 32 output values
__device__ __forceinline__ void epi_pair(int p, const float accE[2][4][4],
                                         char* smem, uint32_t Cepi, uint32_t Aepi,
                                         float* outRow, bool toOut,
                                         int qr, int qc, int nb, int tid) {
    const int im = p >> 3, jn = (p >> 1) & 3, qh = p & 1;
    const int m  = 16 * im + qr + 8 * qh;
    const int n0 = nb + 8 * jn + qc;
    const float2 cp = *reinterpret_cast<const float2*>(
        smem + Cepi + ((p * THREADS + tid) << 3));
    const float t0 = tanhap(accE[im][jn][2 * qh + 0] + cp.x);
    const float t1 = tanhap(accE[im][jn][2 * qh + 1] + cp.y);
    if (toOut) {
        *reinterpret_cast<float2*>(outRow + m * F + n0) = make_float2(t0, t1);
    } else {
        *reinterpret_cast<__half2*>(smem + Aepi + m * ROWB + n0 * 2) =
            __floats2half2_rn(t0, t1);
    }
}

// window: full MMA of one tile (A slot Amma), interleaving another tile's
// epilogue (acc accE -> A slot Aepi / global) one chunk per k-step.
// B: k-steps 0..13 from register cache Bc, 14..15 from the SMEM W-slice.
template <bool DO_EPI, bool EPI_OUT>
__device__ __forceinline__ void window(
    char* smem, uint32_t sb, uint32_t Amma,
    float accM[2][4][4], const float accE[2][4][4],
    uint32_t Aepi, uint32_t Cepi, float* outRow,
    const uint32_t (&Bc)[14][8], uint32_t wk0, uint32_t wk1,
    int a_rowoff, int qr, int qc, int nb, int tid) {
    #pragma unroll
    for (int im = 0; im < 2; im++)
        #pragma unroll
        for (int jn = 0; jn < 4; jn++)
            #pragma unroll
            for (int q = 0; q < 4; q++)
                accM[im][jn][q] = 0.0f;

    const uint32_t abase = sb + Amma + a_rowoff;
    #pragma unroll
    for (int ks = 0; ks < 16; ks++) {
        uint32_t afr0[4], afr1[4];
        ldsm_x4(afr0, abase + ks * 32);
        ldsm_x4(afr1, abase + ks * 32 + 16 * ROWB);

        uint32_t bf[8];
        if (ks < 14) {
            #pragma unroll
            for (int q = 0; q < 8; q++) bf[q] = Bc[ks][q];
        } else {
            ldsm_x4(bf + 0, wk0 + (ks - 14) * 32);
            ldsm_x4(bf + 4, wk1 + (ks - 14) * 32);
        }

        #pragma unroll
        for (int jn = 0; jn < 4; jn++) {
            const uint32_t b0 = bf[(jn >> 1) * 4 + (jn & 1) * 2 + 0];
            const uint32_t b1 = bf[(jn >> 1) * 4 + (jn & 1) * 2 + 1];
            mma16816(accM[0][jn], afr0, b0, b1);
            mma16816(accM[1][jn], afr1, b0, b1);
        }
        if (DO_EPI)
            epi_pair(ks, accE, smem, Cepi, Aepi, outRow, EPI_OUT, qr, qc, nb, tid);
    }
}

// tile prologue: c = x + b -> C buffer (fp32 SoA); z1 = tanh(c) -> A slot 1
__device__ __forceinline__ void tile_prologue(char* smem, uint32_t Aslot1, uint32_t Cbuf,
                                              const float* xRow, const float* b,
                                              int qr, int qc, int nb, int tid) {
    #pragma unroll
    for (int p = 0; p < 16; p++) {
        const int im = p >> 3, jn = (p >> 1) & 3, qh = p & 1;
        const int m  = 16 * im + qr + 8 * qh;
        const int n0 = nb + 8 * jn + qc;
        const float2 xv = *reinterpret_cast<const float2*>(xRow + m * F + n0);
        const float c0 = xv.x + __ldg(b + n0);
        const float c1 = xv.y + __ldg(b + n0 + 1);
        *reinterpret_cast<float2*>(smem + Cbuf + ((p * THREADS + tid) << 3)) =
            make_float2(c0, c1);
        *reinterpret_cast<__half2*>(smem + Aslot1 + m * ROWB + n0 * 2) =
            __floats2half2_rn(tanhap(c0), tanhap(c1));
    }
}

__device__ __forceinline__ void epi_full(const float acc[2][4][4], char* smem,
                                         uint32_t Cbuf, uint32_t Abuf, float* outRow,
                                         bool toOut, int qr, int qc, int nb, int tid) {
    #pragma unroll
    for (int p = 0; p < 16; p++)
        epi_pair(p, acc, smem, Cbuf, Abuf, outRow, toOut, qr, qc, nb, tid);
}

// one pair of rounds (r odd, r and r+1) for the 3-tile rotation; 6 windows,
// 3 barriers. Slot parity fixed: round r reads slot 1, r+1 reads slot 0.
template <bool FIRST, bool LAST>
__device__ __forceinline__ void round_pair(
    char* smem, uint32_t sb,
    float acc0[2][4][4], float acc1[2][4][4], float acc2[2][4][4],
    float* o0, float* o1,
    const uint32_t (&Bc)[14][8], uint32_t wk0, uint32_t wk1,
    int a_rowoff, int qr, int qc, int nb, int tid) {
    // W0: MMA T0(r) rd S0[1] | EPI T2(r-1) wr S2[1]   (skipped on FIRST)
    window<!FIRST, false>(smem, sb, A01, acc0, acc2, A21, C2, nullptr,
                          Bc, wk0, wk1, a_rowoff, qr, qc, nb, tid);
    // W1: MMA T1(r) rd S1[1] | EPI T0(r) wr S0[0]
    window<true, false>(smem, sb, A11, acc1, acc0, A00, C0, nullptr,
                        Bc, wk0, wk1, a_rowoff, qr, qc, nb, tid);
    __syncthreads();
    // W2: MMA T2(r) rd S2[1] | EPI T1(r) wr S1[0]
    window<true, false>(smem, sb, A21, acc2, acc1, A10, C1, nullptr,
                        Bc, wk0, wk1, a_rowoff, qr, qc, nb, tid);
    // W3: MMA T0(r+1) rd S0[0] | EPI T2(r) wr S2[0]
    window<true, false>(smem, sb, A00, acc0, acc2, A20, C2, nullptr,
                        Bc, wk0, wk1, a_rowoff, qr, qc, nb, tid);
    __syncthreads();
    // W4: MMA T1(r+1) rd S1[0] | EPI T0(r+1) wr S0[1] (or OUT on LAST)
    window<true, LAST>(smem, sb, A10, acc1, acc0, A01, C0, o0,
                       Bc, wk0, wk1, a_rowoff, qr, qc, nb, tid);
    // W5: MMA T2(r+1) rd S2[0] | EPI T1(r+1) wr S1[1] (or OUT on LAST)
    window<true, LAST>(smem, sb, A20, acc2, acc1, A11, C1, o1,
                       Bc, wk0, wk1, a_rowoff, qr, qc, nb, tid);
    __syncthreads();
}

__global__ void __launch_bounds__(THREADS, 1)
fixed_point_kernel(const float* __restrict__ x, const float* __restrict__ W,
                   const float* __restrict__ b, float* __restrict__ out) {
    extern __shared__ char smem[];
    const uint32_t sb = smem_u32(smem);
    const int tid = threadIdx.x;
    const int wid = tid >> 5;
    const int lt  = tid & 31;
    const int nb  = wid << 5;

    // ---- 1) W -> SMEM fp16 (temporary, region reused later) ----
    for (int i = tid; i < F * F / 4; i += THREADS) {
        const int n  = i >> 6;
        const int k4 = (i & 63) << 2;
        const float4 wv = *reinterpret_cast<const float4*>(W + n * F + k4);
        __half2* dst = reinterpret_cast<__half2*>(smem + n * ROWB + k4 * 2);
        dst[0] = __floats2half2_rn(wv.x, wv.y);
        dst[1] = __floats2half2_rn(wv.z, wv.w);
    }
    __syncthreads();

    // ---- 2) cache B (W) fragments for k-steps 0..13 in registers (112 regs);
    //          repack k-slice 224..255 into the persistent WK region ----
    const int b_nrow = ((lt >> 4) << 3) + (lt & 7);
    const int b_koff = ((lt >> 3) & 1) << 3;
    uint32_t Bc[14][8];
    #pragma unroll
    for (int ks = 0; ks < 14; ks++) {
        #pragma unroll
        for (int jh = 0; jh < 2; jh++) {
            uint32_t r[4];
            ldsm_x4(r, sb + (nb + 16 * jh + b_nrow) * ROWB + (ks * 16 + b_koff) * 2);
            Bc[ks][jh * 4 + 0] = r[0]; Bc[ks][jh * 4 + 1] = r[1];
            Bc[ks][jh * 4 + 2] = r[2]; Bc[ks][jh * 4 + 3] = r[3];
        }
    }
    {   // copy k-cols 224..255 of each n-row (64B) into WK (stride 80B)
        const int n = tid;   // 256 threads == 256 rows
        const uint4* src = reinterpret_cast<const uint4*>(smem + n * ROWB + 448);
        uint4* dst = reinterpret_cast<uint4*>(smem + SMEM_WK + n * WK_ROWB);
        dst[0] = src[0]; dst[1] = src[1]; dst[2] = src[2]; dst[3] = src[3];
    }
    __syncthreads();   // W region now reusable for A slots + C

    const int qr = lt >> 2, qc = (lt & 3) << 1;
    const int a_rowoff = (lt & 15) * ROWB + ((lt >> 4) << 3) * 2;
    const uint32_t wk0 = sb + SMEM_WK + (nb + b_nrow) * WK_ROWB + b_koff * 2;
    const uint32_t wk1 = sb + SMEM_WK + (nb + 16 + b_nrow) * WK_ROWB + b_koff * 2;

    // ---- schedule: CTAs 0..111 -> 7 tiles (triple+triple+single),
    //                CTAs 112..151 -> 6 tiles (triple+triple) ----
    int start, cnt;
    if (blockIdx.x < 112) { cnt = 7; start = blockIdx.x * 7; }
    else                  { cnt = 6; start = 784 + (blockIdx.x - 112) * 6; }

    float acc0[2][4][4], acc1[2][4][4], acc2[2][4][4];

    int i = 0;
    for (; i + 2 < cnt; i += 3) {
        const float* xT[3];
        float* oT[3];
        #pragma unroll
        for (int t = 0; t < 3; t++) {
            xT[t] = x   + (long)(start + i + t) * MB * F;
            oT[t] = out + (long)(start + i + t) * MB * F;
        }
        tile_prologue(smem, A01, C0, xT[0], b, qr, qc, nb, tid);
        tile_prologue(smem, A11, C1, xT[1], b, qr, qc, nb, tid);
        tile_prologue(smem, A21, C2, xT[2], b, qr, qc, nb, tid);
        __syncthreads();

        round_pair<true, false>(smem, sb, acc0, acc1, acc2, nullptr, nullptr,
                                Bc, wk0, wk1, a_rowoff, qr, qc, nb, tid);
        #pragma unroll 1
        for (int pr = 1; pr < 11; pr++)
            round_pair<false, false>(smem, sb, acc0, acc1, acc2, nullptr, nullptr,
                                     Bc, wk0, wk1, a_rowoff, qr, qc, nb, tid);
        round_pair<false, true>(smem, sb, acc0, acc1, acc2, oT[0], oT[1],
                                Bc, wk0, wk1, a_rowoff, qr, qc, nb, tid);
        // tail: EPI T2(24) -> global (acc2 in registers, no barrier needed)
        epi_full(acc2, smem, C2, 0, oT[2], true, qr, qc, nb, tid);
        __syncthreads();   // before next triple reuses A/C buffers
    }

    if (i < cnt) {   // leftover single tile (serial, 1 barrier/round)
        const float* x0 = x + (long)(start + i) * MB * F;
        float* o0 = out + (long)(start + i) * MB * F;
        tile_prologue(smem, A01, C0, x0, b, qr, qc, nb, tid);
        __syncthreads();
        #pragma unroll 1
        for (int r = 1; r <= 24; r++) {
            const uint32_t Ard = (r & 1) ? A01 : A00;
            const uint32_t Awr = (r & 1) ? A00 : A01;
            window<false, false>(smem, sb, Ard, acc0, acc0, 0, C0, nullptr,
                                 Bc, wk0, wk1, a_rowoff, qr, qc, nb, tid);
            epi_full(acc0, smem, C0, Awr, o0, r == 24, qr, qc, nb, tid);
            __syncthreads();
        }
    }
}

// ============================================================================
// Harness entry
// ============================================================================
extern "C" void kernel_launch(void* const* d_in, const int* in_sizes, int n_in,
                              void* d_out, int out_size) {
    const float* x = (const float*)d_in[0];   // [32768, 256]
    const float* W = (const float*)d_in[1];   // [256, 256]
    const float* b = (const float*)d_in[2];   // [256]
    float* out = (float*)d_out;               // [32768, 256] fp32

    cudaFuncSetAttribute(fixed_point_kernel,
                         cudaFuncAttributeMaxDynamicSharedMemorySize, SMEM_BYTES);
    fixed_point_kernel<<<GRID, THREADS, SMEM_BYTES>>>(x, W, b, out);
}

// round 9
// speedup vs baseline: 1.0075x; 1.0075x over previous
#include <cuda_runtime.h>
#include <cuda_fp16.h>
#include <cstdint>

// ============================================================================
// IterativeFixedPoint: z_{k+1} = tanh(z_k W^T + b + x), z0 = 0, 25 iterations.
// B=32768, F=256.  (sm_103 target: no tcgen05 -> legacy mma.sync HMMA)
//
// R9: 2-tile software pipeline (R7 structure) + EXPLICIT double-buffered
// A-fragment prefetch inside the k-loop (next k-step's ldmatrix issued before
// the current k-step's 8 HMMAs -> LDSM latency hidden per-warp). B (W)
// fragments: 14/16 k-steps cached in registers (112 regs), last 2 k-steps
// from a compact SMEM W-slice, prefetched 2 k-steps ahead. Register budget
// deliberately ~235 (vs 255 cap) so ptxas can schedule, not spill.
// c = x+b in SMEM fp32; tanh.approx epilogue interleaved one pair per k-step;
// z1 = tanh(c) direct (z0=0) -> 24 MMA rounds.
// ============================================================================

static constexpr int F       = 256;
static constexpr int MB      = 32;
static constexpr int THREADS = 256;          // 8 warps
static constexpr int GRID    = 152;
static constexpr int NROUND  = 24;

static constexpr int ROWB    = 528;          // A/W row: 256 halves + 16B pad
static constexpr int A_BYTES = MB * ROWB;    // 16896
// SMEM: region [0, 135168) holds W during init, then reused:
//   A0/A1 z buffers, C0/C1 fp32 c-buffers (all end at 99328 < 135168)
// WK (k=224..255 W slice) lives AFTER the W region, persistent.
static constexpr int SMEM_A0 = 0;
static constexpr int SMEM_A1 = A_BYTES;                    // 16896
static constexpr int SMEM_C0 = 2 * A_BYTES;                // 33792
static constexpr int C_BYTES = 32768;
static constexpr int SMEM_C1 = SMEM_C0 + C_BYTES;          // 66560 (ends 99328)
static constexpr int W_BYTES = F * ROWB;                   // 135168
static constexpr int SMEM_WK = W_BYTES;                    // 135168
static constexpr int WK_ROWB = 80;                         // 64B data + 16B pad
static constexpr int SMEM_BYTES = SMEM_WK + 256 * WK_ROWB; // 155648

__device__ __forceinline__ uint32_t smem_u32(const void* p) {
    uint32_t a;
    asm("{ .reg .u64 t; cvta.to.shared.u64 t, %1; cvt.u32.u64 %0, t; }"
        : "=r"(a) : "l"(p));
    return a;
}

__device__ __forceinline__ void ldsm_x4(uint32_t r[4], uint32_t addr) {
    asm volatile("ldmatrix.sync.aligned.m8n8.x4.shared.b16 {%0,%1,%2,%3}, [%4];"
                 : "=r"(r[0]), "=r"(r[1]), "=r"(r[2]), "=r"(r[3])
                 : "r"(addr));
}

__device__ __forceinline__ void mma16816(float d[4], const uint32_t a[4],
                                         const uint32_t b0, const uint32_t b1) {
    asm volatile(
        "mma.sync.aligned.m16n8k16.row.col.f32.f16.f16.f32 "
        "{%0,%1,%2,%3}, {%4,%5,%6,%7}, {%8,%9}, {%0,%1,%2,%3};"
        : "+f"(d[0]), "+f"(d[1]), "+f"(d[2]), "+f"(d[3])
        : "r"(a[0]), "r"(a[1]), "r"(a[2]), "r"(a[3]), "r"(b0), "r"(b1));
}

__device__ __forceinline__ float tanhap(float s) {
    float r;
    asm("tanh.approx.f32 %0, %1;" : "=f"(r) : "f"(s));
    return r;
}

// one epilogue chunk: pair p (0..15) of this thread's 32 output values
__device__ __forceinline__ void epi_pair(int p, const float accE[2][4][4],
                                         char* smem, uint32_t Cepi, uint32_t Aepi,
                                         float* outRow, bool toOut,
                                         int qr, int qc, int nb, int tid) {
    const int im = p >> 3, jn = (p >> 1) & 3, qh = p & 1;
    const int m  = 16 * im + qr + 8 * qh;
    const int n0 = nb + 8 * jn + qc;
    const float2 cp = *reinterpret_cast<const float2*>(
        smem + Cepi + ((p * THREADS + tid) << 3));
    const float t0 = tanhap(accE[im][jn][2 * qh + 0] + cp.x);
    const float t1 = tanhap(accE[im][jn][2 * qh + 1] + cp.y);
    if (toOut) {
        *reinterpret_cast<float2*>(outRow + m * F + n0) = make_float2(t0, t1);
    } else {
        *reinterpret_cast<__half2*>(smem + Aepi + m * ROWB + n0 * 2) =
            __floats2half2_rn(t0, t1);
    }
}

// window: full MMA round of one tile (reading A slot Amma), with another
// tile's epilogue interleaved one chunk per k-step. A-fragments double-
// buffered and prefetched one k-step ahead; WK B-fragments (ks 14,15)
// prefetched two k-steps ahead.
template <bool DO_EPI, bool EPI_OUT>
__device__ __forceinline__ void window(
    char* smem, uint32_t sb, uint32_t Amma,
    float accM[2][4][4], const float accE[2][4][4],
    uint32_t Aepi, uint32_t Cepi, float* outRow,
    const uint32_t (&Bc)[14][8], uint32_t wk0, uint32_t wk1,
    int a_rowoff, int qr, int qc, int nb, int tid) {
    #pragma unroll
    for (int im = 0; im < 2; im++)
        #pragma unroll
        for (int jn = 0; jn < 4; jn++)
            #pragma unroll
            for (int q = 0; q < 4; q++)
                accM[im][jn][q] = 0.0f;

    const uint32_t abase = sb + Amma + a_rowoff;
    uint32_t afr[2][2][4];   // [buf][m-half][frag]
    uint32_t wkf[2][8];      // B frags for ks 14, 15
    ldsm_x4(afr[0][0], abase);
    ldsm_x4(afr[0][1], abase + 16 * ROWB);

    #pragma unroll
    for (int ks = 0; ks < 16; ks++) {
        const int cur = ks & 1, nxt = cur ^ 1;
        if (ks < 15) {   // prefetch next k-step's A fragments
            ldsm_x4(afr[nxt][0], abase + (ks + 1) * 32);
            ldsm_x4(afr[nxt][1], abase + (ks + 1) * 32 + 16 * ROWB);
        }
        if (ks == 12) { ldsm_x4(wkf[0] + 0, wk0);      ldsm_x4(wkf[0] + 4, wk1); }
        if (ks == 13) { ldsm_x4(wkf[1] + 0, wk0 + 32); ldsm_x4(wkf[1] + 4, wk1 + 32); }

        uint32_t bf[8];
        if (ks < 14) {
            #pragma unroll
            for (int q = 0; q < 8; q++) bf[q] = Bc[ks][q];
        } else {
            #pragma unroll
            for (int q = 0; q < 8; q++) bf[q] = wkf[ks - 14][q];
        }

        #pragma unroll
        for (int jn = 0; jn < 4; jn++) {
            const uint32_t b0 = bf[(jn >> 1) * 4 + (jn & 1) * 2 + 0];
            const uint32_t b1 = bf[(jn >> 1) * 4 + (jn & 1) * 2 + 1];
            mma16816(accM[0][jn], afr[cur][0], b0, b1);
            mma16816(accM[1][jn], afr[cur][1], b0, b1);
        }
        if (DO_EPI)
            epi_pair(ks, accE, smem, Cepi, Aepi, outRow, EPI_OUT, qr, qc, nb, tid);
    }
}

// tile prologue: c = x + b -> C buffer (fp32 SoA); z1 = tanh(c) -> A buffer
__device__ __forceinline__ void tile_prologue(char* smem, uint32_t Abuf, uint32_t Cbuf,
                                              const float* xRow, const float* b,
                                              int qr, int qc, int nb, int tid) {
    #pragma unroll
    for (int p = 0; p < 16; p++) {
        const int im = p >> 3, jn = (p >> 1) & 3, qh = p & 1;
        const int m  = 16 * im + qr + 8 * qh;
        const int n0 = nb + 8 * jn + qc;
        const float2 xv = *reinterpret_cast<const float2*>(xRow + m * F + n0);
        const float c0 = xv.x + __ldg(b + n0);
        const float c1 = xv.y + __ldg(b + n0 + 1);
        *reinterpret_cast<float2*>(smem + Cbuf + ((p * THREADS + tid) << 3)) =
            make_float2(c0, c1);
        *reinterpret_cast<__half2*>(smem + Abuf + m * ROWB + n0 * 2) =
            __floats2half2_rn(tanhap(c0), tanhap(c1));
    }
}

__device__ __forceinline__ void epi_full(const float acc[2][4][4], char* smem,
                                         uint32_t Cbuf, uint32_t Abuf, float* outRow,
                                         bool toOut, int qr, int qc, int nb, int tid) {
    #pragma unroll
    for (int p = 0; p < 16; p++)
        epi_pair(p, acc, smem, Cbuf, Abuf, outRow, toOut, qr, qc, nb, tid);
}

__global__ void __launch_bounds__(THREADS, 1)
fixed_point_kernel(const float* __restrict__ x, const float* __restrict__ W,
                   const float* __restrict__ b, float* __restrict__ out) {
    extern __shared__ char smem[];
    const uint32_t sb = smem_u32(smem);
    const int tid = threadIdx.x;
    const int wid = tid >> 5;
    const int lt  = tid & 31;
    const int nb  = wid << 5;

    // ---- 1) W -> SMEM fp16 (temporary; region reused after caching) ----
    for (int i = tid; i < F * F / 4; i += THREADS) {
        const int n  = i >> 6;
        const int k4 = (i & 63) << 2;
        const float4 wv = *reinterpret_cast<const float4*>(W + n * F + k4);
        __half2* dst = reinterpret_cast<__half2*>(smem + n * ROWB + k4 * 2);
        dst[0] = __floats2half2_rn(wv.x, wv.y);
        dst[1] = __floats2half2_rn(wv.z, wv.w);
    }
    __syncthreads();

    // ---- 2) cache B (W) fragments for k-steps 0..13 in registers;
    //          repack k-cols 224..255 into the persistent WK region ----
    const int b_nrow = ((lt >> 4) << 3) + (lt & 7);
    const int b_koff = ((lt >> 3) & 1) << 3;
    uint32_t Bc[14][8];
    #pragma unroll
    for (int ks = 0; ks < 14; ks++) {
        #pragma unroll
        for (int jh = 0; jh < 2; jh++) {
            uint32_t r[4];
            ldsm_x4(r, sb + (nb + 16 * jh + b_nrow) * ROWB + (ks * 16 + b_koff) * 2);
            Bc[ks][jh * 4 + 0] = r[0]; Bc[ks][jh * 4 + 1] = r[1];
            Bc[ks][jh * 4 + 2] = r[2]; Bc[ks][jh * 4 + 3] = r[3];
        }
    }
    {   // copy k-cols 224..255 of each n-row (64B) into WK (stride 80B)
        const int n = tid;   // 256 threads == 256 rows
        const uint4* src = reinterpret_cast<const uint4*>(smem + n * ROWB + 448);
        uint4* dst = reinterpret_cast<uint4*>(smem + SMEM_WK + n * WK_ROWB);
        dst[0] = src[0]; dst[1] = src[1]; dst[2] = src[2]; dst[3] = src[3];
    }
    __syncthreads();   // W region now reusable for A slots + C

    const int qr = lt >> 2, qc = (lt & 3) << 1;
    const int a_rowoff = (lt & 15) * ROWB + ((lt >> 4) << 3) * 2;
    const uint32_t wk0 = sb + SMEM_WK + (nb + b_nrow) * WK_ROWB + b_koff * 2;
    const uint32_t wk1 = sb + SMEM_WK + (nb + 16 + b_nrow) * WK_ROWB + b_koff * 2;

    // ---- balanced chunk: CTAs 0..111 -> 7 tiles, 112..151 -> 6 tiles ----
    int start, cnt;
    if (blockIdx.x < 112) { cnt = 7; start = blockIdx.x * 7; }
    else                  { cnt = 6; start = 784 + (blockIdx.x - 112) * 6; }

    float acc0[2][4][4], acc1[2][4][4];

    int i = 0;
    for (; i + 1 < cnt; i += 2) {
        const float* x0 = x + (long)(start + i)     * MB * F;
        const float* x1 = x + (long)(start + i + 1) * MB * F;
        float* o0 = out + (long)(start + i)     * MB * F;
        float* o1 = out + (long)(start + i + 1) * MB * F;

        tile_prologue(smem, SMEM_A0, SMEM_C0, x0, b, qr, qc, nb, tid);
        tile_prologue(smem, SMEM_A1, SMEM_C1, x1, b, qr, qc, nb, tid);
        __syncthreads();

        // r=1 fill: MMA T0 (no epi yet)
        window<false, false>(smem, sb, SMEM_A0, acc0, acc1, 0, 0, nullptr,
                             Bc, wk0, wk1, a_rowoff, qr, qc, nb, tid);
        __syncthreads();
        // r=1: MMA T1 + EPI T0(1) -> z2(T0) in-place
        window<true, false>(smem, sb, SMEM_A1, acc1, acc0, SMEM_A0, SMEM_C0,
                            nullptr, Bc, wk0, wk1, a_rowoff, qr, qc, nb, tid);
        __syncthreads();

        #pragma unroll 1
        for (int r = 2; r < NROUND; r++) {
            // MMA T0(r) + EPI T1(r-1)
            window<true, false>(smem, sb, SMEM_A0, acc0, acc1, SMEM_A1, SMEM_C1,
                                nullptr, Bc, wk0, wk1, a_rowoff, qr, qc, nb, tid);
            __syncthreads();
            // MMA T1(r) + EPI T0(r)
            window<true, false>(smem, sb, SMEM_A1, acc1, acc0, SMEM_A0, SMEM_C0,
                                nullptr, Bc, wk0, wk1, a_rowoff, qr, qc, nb, tid);
            __syncthreads();
        }
        // r=24 peeled: MMA T0(24) + EPI T1(23)
        window<true, false>(smem, sb, SMEM_A0, acc0, acc1, SMEM_A1, SMEM_C1,
                            nullptr, Bc, wk0, wk1, a_rowoff, qr, qc, nb, tid);
        __syncthreads();
        // MMA T1(24) + EPI T0(24) -> global out
        window<true, true>(smem, sb, SMEM_A1, acc1, acc0, SMEM_A0, SMEM_C0,
                           o0, Bc, wk0, wk1, a_rowoff, qr, qc, nb, tid);
        // tail: EPI T1(24) -> global out (register acc, no barrier needed)
        epi_full(acc1, smem, SMEM_C1, 0, o1, true, qr, qc, nb, tid);
        __syncthreads();   // before next pair reuses A/C buffers
    }

    if (i < cnt) {   // odd-tile tail: serial single tile, double-buffered A
        const float* x0 = x + (long)(start + i) * MB * F;
        float* o0 = out + (long)(start + i) * MB * F;
        tile_prologue(smem, SMEM_A0, SMEM_C0, x0, b, qr, qc, nb, tid);
        __syncthreads();
        #pragma unroll 1
        for (int r = 1; r <= NROUND; r++) {
            const uint32_t Ard = (r & 1) ? SMEM_A0 : SMEM_A1;
            const uint32_t Awr = (r & 1) ? SMEM_A1 : SMEM_A0;
            window<false, false>(smem, sb, Ard, acc0, acc0, 0, SMEM_C0, nullptr,
                                 Bc, wk0, wk1, a_rowoff, qr, qc, nb, tid);
            epi_full(acc0, smem, SMEM_C0, Awr, o0, r == NROUND, qr, qc, nb, tid);
            __syncthreads();
        }
    }
}

// ============================================================================
// Harness entry
// ============================================================================
extern "C" void kernel_launch(void* const* d_in, const int* in_sizes, int n_in,
                              void* d_out, int out_size) {
    const float* x = (const float*)d_in[0];   // [32768, 256]
    const float* W = (const float*)d_in[1];   // [256, 256]
    const float* b = (const float*)d_in[2];   // [256]
    float* out = (float*)d_out;               // [32768, 256] fp32

    cudaFuncSetAttribute(fixed_point_kernel,
                         cudaFuncAttributeMaxDynamicSharedMemorySize, SMEM_BYTES);
    fixed_point_kernel<<<GRID, THREADS, SMEM_BYTES>>>(x, W, b, out);
}